// round 6
// baseline (speedup 1.0000x reference)
#include <cuda_runtime.h>

// Model_10582799417658: 127-step LSTM-VAE rollout.
// B=4096, D=64, H=256, GATES=1024, L=64, T=128 (127 scan steps).
//
// Round 5: crossbar-balanced retile. Thread tile M_t=8 x J_t=8 (was 4x8):
// LDS:FMA cycle ratio drops 1.5:1 -> 1:1. Single j-pass over all 1024 gate
// cols (PK=8, 40 panels, same sync count), in-place h update, k-major
// pre-transposed weights (round-4 win, kept).

#define B_TOT   4096
#define T_STEPS 127
#define D_IN    64
#define HID     256
#define GATE    1024
#define LAT     64
#define BT      32
#define NTH     512
#define NCTA    (B_TOT / BT)   // 128
#define MS      36             // padded m-stride (floats)
#define PK      8              // phase-1 panel depth (k)
#define NP1     40             // 320 / 8
#define PK2     16             // phase-2 panel depth
#define NP2     16             // 256 / 16
#define SROW2   128

// ---- output layout ----
#define N_STATES ((unsigned long long)B_TOT * T_STEPS * D_IN)
#define N_GENS   ((unsigned long long)B_TOT * T_STEPS)
#define N_TOTS   ((unsigned long long)B_TOT * 128)
#define O_STATES 0ULL
#define O_GENS   (O_STATES + N_STATES)
#define O_ONOFF  (O_GENS + N_GENS)
#define O_TPRE   (O_ONOFF + N_GENS)
#define O_TPOST  (O_TPRE + N_TOTS)

typedef unsigned long long ull;

__device__ float g_wgv[HID];
__device__ float g_wov[HID];
__device__ float g_b2[2];
// k-major transposed weights (filled once):
// g_Wt1[k][r] = (k<64 ? Wih[r][k] : Whh[r][k-64]),  r in [0,1024), k in [0,320)
// g_Wt2[k][r] = (r<64 ? Wmu[r][k] : Wvar[r-64][k]), r in [0,128),  k in [0,256)
__device__ float g_Wt1[320 * 1024];
__device__ float g_Wt2[256 * 128];

__device__ __forceinline__ ull pack2s(float a) {   // splat (a, a)
    ull r;
    asm("mov.b64 %0, {%1,%1};" : "=l"(r) : "r"(__float_as_uint(a)));
    return r;
}
__device__ __forceinline__ void fma2(ull &d, ull a, ull b) {
    asm("fma.rn.f32x2 %0, %1, %2, %0;" : "+l"(d) : "l"(a), "l"(b));
}
__device__ __forceinline__ float2 unpack2(ull v) {
    unsigned int lo, hi;
    asm("mov.b64 {%0,%1}, %2;" : "=r"(lo), "=r"(hi) : "l"(v));
    float2 f; f.x = __uint_as_float(lo); f.y = __uint_as_float(hi);
    return f;
}
__device__ __forceinline__ float sig_f(float x) {
    return 1.0f / (1.0f + __expf(-x));
}
__device__ __forceinline__ float tanh_f(float x) {
    return 1.0f - 2.0f / (__expf(2.0f * x) + 1.0f);
}

// Fold velo/switch heads into rank-1 vectors.
__global__ void prep_kernel(const float* __restrict__ Wgen, const float* __restrict__ bgen,
                            const float* __restrict__ Won,  const float* __restrict__ bon,
                            const float* __restrict__ Wvelo, const float* __restrict__ bvelo,
                            const float* __restrict__ Wsw,  const float* __restrict__ bsw) {
    int k = threadIdx.x;
    float s1 = 0.f, s2 = 0.f;
    #pragma unroll 4
    for (int l = 0; l < LAT; ++l) {
        s1 += Wgen[l] * Wvelo[l * HID + k];
        s2 += Won[l]  * Wsw[l * HID + k];
    }
    g_wgv[k] = s1;
    g_wov[k] = s2;
    if (k == 0) {
        float b1 = bgen[0], b2 = bon[0];
        for (int l = 0; l < LAT; ++l) {
            b1 += Wgen[l] * bvelo[l];
            b2 += Won[l]  * bsw[l];
        }
        g_b2[0] = b1; g_b2[1] = b2;
    }
}

// One-time k-major weight transpose.
__global__ void prep2_kernel(const float* __restrict__ Wih, const float* __restrict__ Whh,
                             const float* __restrict__ Wmu, const float* __restrict__ Wvar) {
    const int stride = gridDim.x * blockDim.x;
    const int idx = blockIdx.x * blockDim.x + threadIdx.x;
    for (int i = idx; i < 320 * 1024; i += stride) {
        int k = i >> 10, r = i & 1023;
        g_Wt1[i] = (k < 64) ? Wih[r * D_IN + k] : Whh[r * HID + (k - 64)];
    }
    for (int i = idx; i < 256 * 128; i += stride) {
        int k = i >> 7, r = i & 127;
        g_Wt2[i] = (r < 64) ? Wmu[r * HID + k] : Wvar[(r - 64) * HID + k];
    }
}

__global__ void __launch_bounds__(NTH, 1)
model_kernel(const float* __restrict__ data, const float* __restrict__ locs,
             const float* __restrict__ bih,  const float* __restrict__ bhh,
             const float* __restrict__ bmu,  const float* __restrict__ bvar,
             const float* __restrict__ Wnext, const float* __restrict__ bnext,
             const float* __restrict__ Wloc, const float* __restrict__ bloc,
             const float* __restrict__ eps,  float* __restrict__ out) {
    extern __shared__ float sm[];
    float* xs     = sm;                  // [64][MS]
    float* hs     = xs     + 2304;       // [256][MS]  in-place h
    float* cs     = hs     + 9216;       // [256][MS]
    float* zs     = cs     + 9216;       // [64][MS]
    float* bsum   = zs     + 2304;       // [1024]
    float* wgv    = bsum   + 1024;       // [256]
    float* wov    = wgv    + 256;        // [256]
    float* bmu_s  = wov    + 256;        // [64]
    float* bvar_s = bmu_s  + 64;         // [64]
    float* bnx_s  = bvar_s + 64;         // [64]
    float* wnT    = bnx_s  + 64;         // [64][64]
    float* abuf   = wnT    + 4096;       // [32]
    float* wbA    = abuf   + 32;         // [PK][1024] panel A (8192)
    float* wbB    = wbA    + 8192;       // panel B (8192)
    float* mus    = wbA;                 // [64][MS]  (reuse after phase 2a)
    float* lvs    = wbA + 2304;          // [64][MS]
    float* wbuf[2] = { wbA, wbB };

    const int tid   = threadIdx.x;
    const int bBase = blockIdx.x * BT;
    // phase-1 compute tile: 4 m-tiles of 8 rows x 128 j-pairs (covers 1024 cols)
    const int m0A  = (tid & 3) * 8;
    const int jt2A = (tid >> 2) * 2;     // 0..254 (col pair within each gate blk)
    const int wrp = tid >> 5, lane = tid & 31;
    // phase-2a tile (round-4 proven): 8 m-tiles of 4 x 64 row-pairs
    const int m08 = (tid & 7) * 4;
    const int jq2 = (tid >> 3) * 2;      // 0..126
    const int k_l = tid >> 5;            // 0..15
    const int r4  = (tid & 31) * 4;

    // ---------------- init ----------------
    for (int i = tid; i < HID * MS; i += NTH) cs[i] = 0.f;
    for (int i = tid; i < D_IN * BT; i += NTH) {
        int k = i / BT, m = i % BT;
        xs[k * MS + m] = data[(size_t)(bBase + m) * (128 * D_IN) + k];
    }
    for (int i = tid; i < HID * BT; i += NTH) {
        int j = i / BT, m = i % BT;
        int b = bBase + m;
        hs[j * MS + m] = locs[b * 2] * Wloc[j * 2] + locs[b * 2 + 1] * Wloc[j * 2 + 1] + bloc[j];
    }
    for (int i = tid; i < GATE; i += NTH) bsum[i] = bih[i] + bhh[i];
    for (int i = tid; i < HID; i += NTH) { wgv[i] = g_wgv[i]; wov[i] = g_wov[i]; }
    for (int i = tid; i < LAT; i += NTH) { bmu_s[i] = bmu[i]; bvar_s[i] = bvar[i]; }
    for (int i = tid; i < D_IN; i += NTH) bnx_s[i] = bnext[i];
    for (int i = tid; i < LAT * D_IN; i += NTH) {   // wnT[l][c] = Wnext[c][l]
        int l = i >> 6, c = i & 63;
        wnT[i] = Wnext[c * LAT + l];
    }
    if (tid < BT) {
        out[O_TPRE  + (size_t)(bBase + tid) * 128] = 0.f;
        out[O_TPOST + (size_t)(bBase + tid) * 128] = 0.f;
    }
    const float bgv = g_b2[0], bov = g_b2[1];
    __syncthreads();

    for (int t = 0; t < T_STEPS; ++t) {
        // prefetch eps for phase 2b
        float ea[2], eb[2];
        {
            const int mr = wrp * 2;
            const float* ep = eps + ((size_t)t * B_TOT + bBase + mr) * LAT;
            ea[0] = __ldg(ep + lane);        eb[0] = __ldg(ep + lane + 32);
            ea[1] = __ldg(ep + LAT + lane);  eb[1] = __ldg(ep + LAT + lane + 32);
        }

        // ======== Phase 1: gates = x@Wih^T + h@Whh^T, LSTM update ========
        {
            auto ld1 = [&](int p, float4* pf) {
                const float4* src = ((const float4*)g_Wt1) + (size_t)p * 2048 + tid;
                pf[0] = __ldg(src);
                pf[1] = __ldg(src + 512);
                pf[2] = __ldg(src + 1024);
                pf[3] = __ldg(src + 1536);
            };
            auto st1 = [&](int p, const float4* pf) {
                float4* dst = ((float4*)wbuf[p & 1]) + tid;
                dst[0]    = pf[0];
                dst[512]  = pf[1];
                dst[1024] = pf[2];
                dst[1536] = pf[3];
            };

            ull acc[32];                 // acc[m*4+g]: j-pair for (m, gate g)
            #pragma unroll
            for (int i = 0; i < 32; ++i) acc[i] = 0ULL;

            float4 pf[4];
            { float4 t0[4]; ld1(0, t0); st1(0, t0); }
            ld1(1, pf);
            __syncthreads();

            for (int p = 0; p < NP1; ++p) {
                if (p + 1 < NP1) st1(p + 1, pf);
                if (p + 2 < NP1) ld1(p + 2, pf);
                const float* wc = wbuf[p & 1];
                const float* Ab = (p < 8) ? (xs + p * PK * MS)
                                          : (hs + (p * PK - 64) * MS);
                #pragma unroll
                for (int kk = 0; kk < PK; ++kk) {
                    float4 a0 = *(const float4*)(Ab + kk * MS + m0A);
                    float4 a1 = *(const float4*)(Ab + kk * MS + m0A + 4);
                    const float* wr = wc + kk * 1024 + jt2A;
                    ull w0 = *(const ull*)(wr);
                    ull w1 = *(const ull*)(wr + 256);
                    ull w2 = *(const ull*)(wr + 512);
                    ull w3 = *(const ull*)(wr + 768);
                    #pragma unroll
                    for (int m = 0; m < 4; ++m) {
                        ull am = pack2s((&a0.x)[m]);
                        fma2(acc[m * 4 + 0], am, w0);
                        fma2(acc[m * 4 + 1], am, w1);
                        fma2(acc[m * 4 + 2], am, w2);
                        fma2(acc[m * 4 + 3], am, w3);
                    }
                    #pragma unroll
                    for (int m = 0; m < 4; ++m) {
                        ull am = pack2s((&a1.x)[m]);
                        fma2(acc[(m + 4) * 4 + 0], am, w0);
                        fma2(acc[(m + 4) * 4 + 1], am, w1);
                        fma2(acc[(m + 4) * 4 + 2], am, w2);
                        fma2(acc[(m + 4) * 4 + 3], am, w3);
                    }
                }
                __syncthreads();
            }

            // epilogue: bias + LSTM nonlinearity for hidden col pair, 8 m rows
            const int hj0 = jt2A, hj1 = jt2A + 1;
            const float bi0 = bsum[hj0],       bi1 = bsum[hj1];
            const float bf0 = bsum[256 + hj0], bf1 = bsum[256 + hj1];
            const float bg0 = bsum[512 + hj0], bg1 = bsum[512 + hj1];
            const float bo0 = bsum[768 + hj0], bo1 = bsum[768 + hj1];
            #pragma unroll
            for (int m = 0; m < 8; ++m) {
                const int mm = m0A + m;
                float2 vi = unpack2(acc[m * 4 + 0]);
                float2 vf = unpack2(acc[m * 4 + 1]);
                float2 vg = unpack2(acc[m * 4 + 2]);
                float2 vo = unpack2(acc[m * 4 + 3]);
                {
                    float iv = sig_f(vi.x + bi0), fv = sig_f(vf.x + bf0);
                    float gv = tanh_f(vg.x + bg0), ov = sig_f(vo.x + bo0);
                    float c = fv * cs[hj0 * MS + mm] + iv * gv;
                    cs[hj0 * MS + mm] = c;
                    hs[hj0 * MS + mm] = ov * tanh_f(c);
                }
                {
                    float iv = sig_f(vi.y + bi1), fv = sig_f(vf.y + bf1);
                    float gv = tanh_f(vg.y + bg1), ov = sig_f(vo.y + bo1);
                    float c = fv * cs[hj1 * MS + mm] + iv * gv;
                    cs[hj1 * MS + mm] = c;
                    hs[hj1 * MS + mm] = ov * tanh_f(c);
                }
            }
        }

        // ======== Phase 2a: [mu;logvar] = h @ [Wmu;Wvar]^T ========
        {
            auto ld2 = [&](int p, float4* pf) {
                *pf = __ldg((const float4*)(g_Wt2 + (size_t)(p * PK2 + k_l) * 128 + r4));
            };
            auto st2 = [&](int p, const float4* pf) {
                *(float4*)(wbuf[p & 1] + k_l * SROW2 + r4) = *pf;
            };

            ull acc2[4] = {0ULL, 0ULL, 0ULL, 0ULL};
            float4 pf2;
            { float4 t0; ld2(0, &t0); st2(0, &t0); }
            ld2(1, &pf2);
            __syncthreads();

            for (int p = 0; p < NP2; ++p) {
                if (p + 1 < NP2) st2(p + 1, &pf2);
                if (p + 2 < NP2) ld2(p + 2, &pf2);
                const float* wc = wbuf[p & 1];
                const int k0 = p * PK2;
                #pragma unroll
                for (int kk = 0; kk < PK2; ++kk) {
                    float4 a = *(const float4*)(hs + (k0 + kk) * MS + m08);
                    ull w = *(const ull*)(wc + kk * SROW2 + jq2);
                    fma2(acc2[0], pack2s(a.x), w);
                    fma2(acc2[1], pack2s(a.y), w);
                    fma2(acc2[2], pack2s(a.z), w);
                    fma2(acc2[3], pack2s(a.w), w);
                }
                __syncthreads();
            }
            // epilogue: output row pair (jq2, jq2+1) for 4 m rows
            if (jq2 < 64) {
                const float b0 = bmu_s[jq2], b1 = bmu_s[jq2 + 1];
                #pragma unroll
                for (int m = 0; m < 4; ++m) {
                    float2 v = unpack2(acc2[m]);
                    mus[jq2 * MS + m08 + m]       = v.x + b0;
                    mus[(jq2 + 1) * MS + m08 + m] = v.y + b1;
                }
            } else {
                const int l0 = jq2 - 64;
                const float b0 = bvar_s[l0], b1 = bvar_s[l0 + 1];
                #pragma unroll
                for (int m = 0; m < 4; ++m) {
                    float2 v = unpack2(acc2[m]);
                    lvs[l0 * MS + m08 + m]       = v.x + b0;
                    lvs[(l0 + 1) * MS + m08 + m] = v.y + b1;
                }
            }
        }
        __syncthreads();

        // ======== Phase 2b: gen/on + reparameterized z ========
        #pragma unroll
        for (int r = 0; r < 2; ++r) {
            const int m = wrp * 2 + r;
            const int b = bBase + m;
            float gp = 0.f, op = 0.f;
            #pragma unroll
            for (int i2 = 0; i2 < 8; ++i2) {
                int k = lane + 32 * i2;
                float hv = hs[k * MS + m];
                gp = fmaf(hv, wgv[k], gp);
                op = fmaf(hv, wov[k], op);
            }
            #pragma unroll
            for (int s2 = 16; s2 > 0; s2 >>= 1) {
                gp += __shfl_xor_sync(0xffffffffu, gp, s2);
                op += __shfl_xor_sync(0xffffffffu, op, s2);
            }
            if (lane == 0) {
                float gen = fmaxf(gp + bgv, 0.f);
                float on  = (op + bov) > 0.f ? 1.f : 0.f;
                abuf[m] = gen * on;
                out[O_GENS  + (size_t)b * T_STEPS + t] = gen;
                out[O_ONOFF + (size_t)b * T_STEPS + t] = on;
            }
            float mu0 = mus[lane * MS + m],        lv0 = lvs[lane * MS + m];
            float mu1 = mus[(lane + 32) * MS + m], lv1 = lvs[(lane + 32) * MS + m];
            zs[lane * MS + m]        = ea[r] * __expf(0.5f * lv0) + mu0;
            zs[(lane + 32) * MS + m] = eb[r] * __expf(0.5f * lv1) + mu1;
        }
        __syncwarp();

        // ======== Phase 3: delta = z@Wnext^T, state update, totals ========
        #pragma unroll
        for (int r = 0; r < 2; ++r) {
            const int m = wrp * 2 + r;
            const int b = bBase + m;
            float d0 = bnx_s[lane], d1 = bnx_s[lane + 32];
            #pragma unroll 8
            for (int l = 0; l < LAT; ++l) {
                float zl = zs[l * MS + m];
                d0 = fmaf(zl, wnT[l * 64 + lane],      d0);
                d1 = fmaf(zl, wnT[l * 64 + lane + 32], d1);
            }
            float xn0 = (lane == 0) ? 0.f : fmaxf(xs[lane * MS + m] + d0, 0.f);
            float xn1 = fmaxf(xs[(lane + 32) * MS + m] + d1, 0.f);
            float part = xn0 + xn1;
            #pragma unroll
            for (int s2 = 16; s2 > 0; s2 >>= 1)
                part += __shfl_xor_sync(0xffffffffu, part, s2);
            float add = abuf[m];
            float v0 = (lane == 0) ? add : xn0;
            size_t ob = O_STATES + ((size_t)b * T_STEPS + t) * D_IN;
            out[ob + lane]      = v0;
            out[ob + lane + 32] = xn1;
            xs[lane * MS + m]        = v0;
            xs[(lane + 32) * MS + m] = xn1;
            if (lane == 0) {
                out[O_TPRE  + (size_t)b * 128 + t + 1] = part;
                out[O_TPOST + (size_t)b * 128 + t + 1] = part + add;
            }
        }
        __syncthreads();
    }
}

extern "C" void kernel_launch(void* const* d_in, const int* in_sizes, int n_in,
                              void* d_out, int out_size) {
    const float* data  = (const float*)d_in[0];
    const float* locs  = (const float*)d_in[1];
    const float* Wih   = (const float*)d_in[2];
    const float* Whh   = (const float*)d_in[3];
    const float* bih   = (const float*)d_in[4];
    const float* bhh   = (const float*)d_in[5];
    const float* Wmu   = (const float*)d_in[6];
    const float* bmu   = (const float*)d_in[7];
    const float* Wvar  = (const float*)d_in[8];
    const float* bvar  = (const float*)d_in[9];
    const float* Wvelo = (const float*)d_in[10];
    const float* bvelo = (const float*)d_in[11];
    const float* Wsw   = (const float*)d_in[12];
    const float* bsw   = (const float*)d_in[13];
    const float* Wgen  = (const float*)d_in[14];
    const float* bgen  = (const float*)d_in[15];
    const float* Won   = (const float*)d_in[16];
    const float* bon   = (const float*)d_in[17];
    const float* Wnext = (const float*)d_in[18];
    const float* bnext = (const float*)d_in[19];
    const float* Wloc  = (const float*)d_in[20];
    const float* bloc  = (const float*)d_in[21];
    const float* eps   = (const float*)d_in[22];
    float* out = (float*)d_out;

    prep_kernel<<<1, 256>>>(Wgen, bgen, Won, bon, Wvelo, bvelo, Wsw, bsw);
    prep2_kernel<<<256, 512>>>(Wih, Whh, Wmu, Wvar);

    // floats: 2304+9216+9216+2304+1024+256+256+64+64+64+4096+32+8192+8192
    const size_t smem_bytes = 45280 * sizeof(float);  // 181,120 B
    cudaFuncSetAttribute(model_kernel,
                         cudaFuncAttributeMaxDynamicSharedMemorySize,
                         (int)smem_bytes);
    model_kernel<<<NCTA, NTH, smem_bytes>>>(data, locs, bih, bhh,
                                            bmu, bvar, Wnext, bnext,
                                            Wloc, bloc, eps, out);
}

// round 7
// speedup vs baseline: 1.2770x; 1.2770x over previous
#include <cuda_runtime.h>

// Model_10582799417658: 127-step LSTM-VAE rollout.
// B=4096, D=64, H=256, GATES=1024, L=64, T=128 (127 scan steps).
//
// Round 7: cp.async (LDGSTS) 3-stage panel ring replaces LDG->reg->STS
// staging. Frees ~20 regs/thread (round 5 was at the 128-reg cap with 64
// accumulator regs -> spills), removes STS issue from the hot loop, and
// bypasses L1 on weight fills. Phase-2a panels deepened to PK2=32 (8 syncs).

#define B_TOT   4096
#define T_STEPS 127
#define D_IN    64
#define HID     256
#define GATE    1024
#define LAT     64
#define BT      32
#define NTH     512
#define NCTA    (B_TOT / BT)   // 128
#define MS      36             // padded m-stride (floats)
#define PK      8              // phase-1 panel depth (k)
#define NP1     40             // 320 / 8
#define PK2     32             // phase-2 panel depth
#define NP2     8              // 256 / 32
#define SLOTF   8192           // floats per panel slot (32 KB)

// ---- output layout ----
#define N_STATES ((unsigned long long)B_TOT * T_STEPS * D_IN)
#define N_GENS   ((unsigned long long)B_TOT * T_STEPS)
#define N_TOTS   ((unsigned long long)B_TOT * 128)
#define O_STATES 0ULL
#define O_GENS   (O_STATES + N_STATES)
#define O_ONOFF  (O_GENS + N_GENS)
#define O_TPRE   (O_ONOFF + N_GENS)
#define O_TPOST  (O_TPRE + N_TOTS)

typedef unsigned long long ull;

__device__ float g_wgv[HID];
__device__ float g_wov[HID];
__device__ float g_b2[2];
// k-major transposed weights (filled once):
// g_Wt1[k][r] = (k<64 ? Wih[r][k] : Whh[r][k-64]),  r in [0,1024), k in [0,320)
// g_Wt2[k][r] = (r<64 ? Wmu[r][k] : Wvar[r-64][k]), r in [0,128),  k in [0,256)
__device__ float g_Wt1[320 * 1024];
__device__ float g_Wt2[256 * 128];

__device__ __forceinline__ ull pack2s(float a) {   // splat (a, a)
    ull r;
    asm("mov.b64 %0, {%1,%1};" : "=l"(r) : "r"(__float_as_uint(a)));
    return r;
}
__device__ __forceinline__ void fma2(ull &d, ull a, ull b) {
    asm("fma.rn.f32x2 %0, %1, %2, %0;" : "+l"(d) : "l"(a), "l"(b));
}
__device__ __forceinline__ float2 unpack2(ull v) {
    unsigned int lo, hi;
    asm("mov.b64 {%0,%1}, %2;" : "=r"(lo), "=r"(hi) : "l"(v));
    float2 f; f.x = __uint_as_float(lo); f.y = __uint_as_float(hi);
    return f;
}
__device__ __forceinline__ float sig_f(float x) {
    return 1.0f / (1.0f + __expf(-x));
}
__device__ __forceinline__ float tanh_f(float x) {
    return 1.0f - 2.0f / (__expf(2.0f * x) + 1.0f);
}
__device__ __forceinline__ void cpa16(unsigned int dst, const void* src) {
    asm volatile("cp.async.cg.shared.global [%0], [%1], 16;" :: "r"(dst), "l"(src));
}
__device__ __forceinline__ void cpa_commit() {
    asm volatile("cp.async.commit_group;");
}
__device__ __forceinline__ void cpa_wait1() {
    asm volatile("cp.async.wait_group 1;");
}

// Fold velo/switch heads into rank-1 vectors.
__global__ void prep_kernel(const float* __restrict__ Wgen, const float* __restrict__ bgen,
                            const float* __restrict__ Won,  const float* __restrict__ bon,
                            const float* __restrict__ Wvelo, const float* __restrict__ bvelo,
                            const float* __restrict__ Wsw,  const float* __restrict__ bsw) {
    int k = threadIdx.x;
    float s1 = 0.f, s2 = 0.f;
    #pragma unroll 4
    for (int l = 0; l < LAT; ++l) {
        s1 += Wgen[l] * Wvelo[l * HID + k];
        s2 += Won[l]  * Wsw[l * HID + k];
    }
    g_wgv[k] = s1;
    g_wov[k] = s2;
    if (k == 0) {
        float b1 = bgen[0], b2 = bon[0];
        for (int l = 0; l < LAT; ++l) {
            b1 += Wgen[l] * bvelo[l];
            b2 += Won[l]  * bsw[l];
        }
        g_b2[0] = b1; g_b2[1] = b2;
    }
}

// One-time k-major weight transpose.
__global__ void prep2_kernel(const float* __restrict__ Wih, const float* __restrict__ Whh,
                             const float* __restrict__ Wmu, const float* __restrict__ Wvar) {
    const int stride = gridDim.x * blockDim.x;
    const int idx = blockIdx.x * blockDim.x + threadIdx.x;
    for (int i = idx; i < 320 * 1024; i += stride) {
        int k = i >> 10, r = i & 1023;
        g_Wt1[i] = (k < 64) ? Wih[r * D_IN + k] : Whh[r * HID + (k - 64)];
    }
    for (int i = idx; i < 256 * 128; i += stride) {
        int k = i >> 7, r = i & 127;
        g_Wt2[i] = (r < 64) ? Wmu[r * HID + k] : Wvar[(r - 64) * HID + k];
    }
}

__global__ void __launch_bounds__(NTH, 1)
model_kernel(const float* __restrict__ data, const float* __restrict__ locs,
             const float* __restrict__ bih,  const float* __restrict__ bhh,
             const float* __restrict__ bmu,  const float* __restrict__ bvar,
             const float* __restrict__ Wnext, const float* __restrict__ bnext,
             const float* __restrict__ Wloc, const float* __restrict__ bloc,
             const float* __restrict__ eps,  float* __restrict__ out) {
    extern __shared__ float sm[];
    float* xs     = sm;                  // [64][MS]
    float* hs     = xs     + 2304;       // [256][MS]  in-place h
    float* cs     = hs     + 9216;       // [256][MS]
    float* zs     = cs     + 9216;       // [64][MS]
    float* bsum   = zs     + 2304;       // [1024]
    float* wgv    = bsum   + 1024;       // [256]
    float* wov    = wgv    + 256;        // [256]
    float* bmu_s  = wov    + 256;        // [64]
    float* bvar_s = bmu_s  + 64;         // [64]
    float* bnx_s  = bvar_s + 64;         // [64]
    float* wnT    = bnx_s  + 64;         // [64][64]
    float* abuf   = wnT    + 4096;       // [32]
    float* wbA    = abuf   + 32;         // 3 panel slots of SLOTF floats
    float* mus    = wbA;                 // [64][MS]  (reuse slot0 after 2a)
    float* lvs    = wbA + 2304;          // [64][MS]

    const unsigned int wb_u32 =
        (unsigned int)__cvta_generic_to_shared(wbA);

    const int tid   = threadIdx.x;
    const int bBase = blockIdx.x * BT;
    // phase-1 compute tile: 4 m-tiles of 8 rows x 128 j-pairs
    const int m0A  = (tid & 3) * 8;
    const int jt2A = (tid >> 2) * 2;
    const int wrp = tid >> 5, lane = tid & 31;
    // phase-2a tile: 8 m-tiles of 4 x 64 row-pairs
    const int m08 = (tid & 7) * 4;
    const int jq2 = (tid >> 3) * 2;

    // ---------------- init ----------------
    for (int i = tid; i < HID * MS; i += NTH) cs[i] = 0.f;
    for (int i = tid; i < D_IN * BT; i += NTH) {
        int k = i / BT, m = i % BT;
        xs[k * MS + m] = data[(size_t)(bBase + m) * (128 * D_IN) + k];
    }
    for (int i = tid; i < HID * BT; i += NTH) {
        int j = i / BT, m = i % BT;
        int b = bBase + m;
        hs[j * MS + m] = locs[b * 2] * Wloc[j * 2] + locs[b * 2 + 1] * Wloc[j * 2 + 1] + bloc[j];
    }
    for (int i = tid; i < GATE; i += NTH) bsum[i] = bih[i] + bhh[i];
    for (int i = tid; i < HID; i += NTH) { wgv[i] = g_wgv[i]; wov[i] = g_wov[i]; }
    for (int i = tid; i < LAT; i += NTH) { bmu_s[i] = bmu[i]; bvar_s[i] = bvar[i]; }
    for (int i = tid; i < D_IN; i += NTH) bnx_s[i] = bnext[i];
    for (int i = tid; i < LAT * D_IN; i += NTH) {   // wnT[l][c] = Wnext[c][l]
        int l = i >> 6, c = i & 63;
        wnT[i] = Wnext[c * LAT + l];
    }
    if (tid < BT) {
        out[O_TPRE  + (size_t)(bBase + tid) * 128] = 0.f;
        out[O_TPOST + (size_t)(bBase + tid) * 128] = 0.f;
    }
    const float bgv = g_b2[0], bov = g_b2[1];
    __syncthreads();

    // panel issue helpers (cp.async, 16B granules)
    auto issue1 = [&](int p, int slot) {
        const float4* src = ((const float4*)g_Wt1) + (size_t)p * 2048 + tid;
        unsigned int dst = wb_u32 + (unsigned int)slot * (SLOTF * 4u) + tid * 16u;
        cpa16(dst,          src);
        cpa16(dst + 8192u,  src + 512);
        cpa16(dst + 16384u, src + 1024);
        cpa16(dst + 24576u, src + 1536);
    };
    auto issue2 = [&](int p, int slot) {
        const float4* src = ((const float4*)g_Wt2) + (size_t)p * 1024 + tid;
        unsigned int dst = wb_u32 + (unsigned int)slot * (SLOTF * 4u) + tid * 16u;
        cpa16(dst,         src);
        cpa16(dst + 8192u, src + 512);
    };

    for (int t = 0; t < T_STEPS; ++t) {
        // prefetch eps for phase 2b
        float ea[2], eb[2];
        {
            const int mr = wrp * 2;
            const float* ep = eps + ((size_t)t * B_TOT + bBase + mr) * LAT;
            ea[0] = __ldg(ep + lane);        eb[0] = __ldg(ep + lane + 32);
            ea[1] = __ldg(ep + LAT + lane);  eb[1] = __ldg(ep + LAT + lane + 32);
        }

        // ======== Phase 1: gates = x@Wih^T + h@Whh^T, LSTM update ========
        {
            issue1(0, 0); cpa_commit();
            issue1(1, 1); cpa_commit();

            ull acc[32];
            #pragma unroll
            for (int i = 0; i < 32; ++i) acc[i] = 0ULL;

            for (int p = 0; p < NP1; ++p) {
                cpa_wait1();
                __syncthreads();     // panel p visible; slot (p+2)%3 free
                if (p + 2 < NP1) issue1(p + 2, (p + 2) % 3);
                cpa_commit();
                const float* wc = wbA + (p % 3) * SLOTF;
                const float* Ab = (p < 8) ? (xs + p * PK * MS)
                                          : (hs + (p * PK - 64) * MS);
                #pragma unroll
                for (int kk = 0; kk < PK; ++kk) {
                    float4 a0 = *(const float4*)(Ab + kk * MS + m0A);
                    float4 a1 = *(const float4*)(Ab + kk * MS + m0A + 4);
                    const float* wr = wc + kk * 1024 + jt2A;
                    ull w0 = *(const ull*)(wr);
                    ull w1 = *(const ull*)(wr + 256);
                    ull w2 = *(const ull*)(wr + 512);
                    ull w3 = *(const ull*)(wr + 768);
                    #pragma unroll
                    for (int m = 0; m < 4; ++m) {
                        ull am = pack2s((&a0.x)[m]);
                        fma2(acc[m * 4 + 0], am, w0);
                        fma2(acc[m * 4 + 1], am, w1);
                        fma2(acc[m * 4 + 2], am, w2);
                        fma2(acc[m * 4 + 3], am, w3);
                    }
                    #pragma unroll
                    for (int m = 0; m < 4; ++m) {
                        ull am = pack2s((&a1.x)[m]);
                        fma2(acc[(m + 4) * 4 + 0], am, w0);
                        fma2(acc[(m + 4) * 4 + 1], am, w1);
                        fma2(acc[(m + 4) * 4 + 2], am, w2);
                        fma2(acc[(m + 4) * 4 + 3], am, w3);
                    }
                }
            }
            __syncthreads();         // all warps done reading hs/panels

            // epilogue: bias + LSTM nonlinearity, h/c in place
            const int hj0 = jt2A, hj1 = jt2A + 1;
            const float bi0 = bsum[hj0],       bi1 = bsum[hj1];
            const float bf0 = bsum[256 + hj0], bf1 = bsum[256 + hj1];
            const float bg0 = bsum[512 + hj0], bg1 = bsum[512 + hj1];
            const float bo0 = bsum[768 + hj0], bo1 = bsum[768 + hj1];
            #pragma unroll
            for (int m = 0; m < 8; ++m) {
                const int mm = m0A + m;
                float2 vi = unpack2(acc[m * 4 + 0]);
                float2 vf = unpack2(acc[m * 4 + 1]);
                float2 vg = unpack2(acc[m * 4 + 2]);
                float2 vo = unpack2(acc[m * 4 + 3]);
                {
                    float iv = sig_f(vi.x + bi0), fv = sig_f(vf.x + bf0);
                    float gv = tanh_f(vg.x + bg0), ov = sig_f(vo.x + bo0);
                    float c = fv * cs[hj0 * MS + mm] + iv * gv;
                    cs[hj0 * MS + mm] = c;
                    hs[hj0 * MS + mm] = ov * tanh_f(c);
                }
                {
                    float iv = sig_f(vi.y + bi1), fv = sig_f(vf.y + bf1);
                    float gv = tanh_f(vg.y + bg1), ov = sig_f(vo.y + bo1);
                    float c = fv * cs[hj1 * MS + mm] + iv * gv;
                    cs[hj1 * MS + mm] = c;
                    hs[hj1 * MS + mm] = ov * tanh_f(c);
                }
            }
        }

        // ======== Phase 2a: [mu;logvar] = h @ [Wmu;Wvar]^T ========
        {
            issue2(0, 0); cpa_commit();
            issue2(1, 1); cpa_commit();

            ull acc2[4] = {0ULL, 0ULL, 0ULL, 0ULL};

            for (int p = 0; p < NP2; ++p) {
                cpa_wait1();
                __syncthreads();     // also orders phase-1 hs writes at p=0
                if (p + 2 < NP2) issue2(p + 2, (p + 2) % 3);
                cpa_commit();
                const float* wc = wbA + (p % 3) * SLOTF;
                const int k0 = p * PK2;
                #pragma unroll
                for (int kk = 0; kk < PK2; ++kk) {
                    float4 a = *(const float4*)(hs + (k0 + kk) * MS + m08);
                    ull w = *(const ull*)(wc + kk * 128 + jq2);
                    fma2(acc2[0], pack2s(a.x), w);
                    fma2(acc2[1], pack2s(a.y), w);
                    fma2(acc2[2], pack2s(a.z), w);
                    fma2(acc2[3], pack2s(a.w), w);
                }
            }
            __syncthreads();         // all warps done with panel slots

            // epilogue: row pair (jq2, jq2+1) for 4 m rows -> mus/lvs (slot0)
            if (jq2 < 64) {
                const float b0 = bmu_s[jq2], b1 = bmu_s[jq2 + 1];
                #pragma unroll
                for (int m = 0; m < 4; ++m) {
                    float2 v = unpack2(acc2[m]);
                    mus[jq2 * MS + m08 + m]       = v.x + b0;
                    mus[(jq2 + 1) * MS + m08 + m] = v.y + b1;
                }
            } else {
                const int l0 = jq2 - 64;
                const float b0 = bvar_s[l0], b1 = bvar_s[l0 + 1];
                #pragma unroll
                for (int m = 0; m < 4; ++m) {
                    float2 v = unpack2(acc2[m]);
                    lvs[l0 * MS + m08 + m]       = v.x + b0;
                    lvs[(l0 + 1) * MS + m08 + m] = v.y + b1;
                }
            }
        }
        __syncthreads();

        // ======== Phase 2b: gen/on + reparameterized z ========
        #pragma unroll
        for (int r = 0; r < 2; ++r) {
            const int m = wrp * 2 + r;
            const int b = bBase + m;
            float gp = 0.f, op = 0.f;
            #pragma unroll
            for (int i2 = 0; i2 < 8; ++i2) {
                int k = lane + 32 * i2;
                float hv = hs[k * MS + m];
                gp = fmaf(hv, wgv[k], gp);
                op = fmaf(hv, wov[k], op);
            }
            #pragma unroll
            for (int s2 = 16; s2 > 0; s2 >>= 1) {
                gp += __shfl_xor_sync(0xffffffffu, gp, s2);
                op += __shfl_xor_sync(0xffffffffu, op, s2);
            }
            if (lane == 0) {
                float gen = fmaxf(gp + bgv, 0.f);
                float on  = (op + bov) > 0.f ? 1.f : 0.f;
                abuf[m] = gen * on;
                out[O_GENS  + (size_t)b * T_STEPS + t] = gen;
                out[O_ONOFF + (size_t)b * T_STEPS + t] = on;
            }
            float mu0 = mus[lane * MS + m],        lv0 = lvs[lane * MS + m];
            float mu1 = mus[(lane + 32) * MS + m], lv1 = lvs[(lane + 32) * MS + m];
            zs[lane * MS + m]        = ea[r] * __expf(0.5f * lv0) + mu0;
            zs[(lane + 32) * MS + m] = eb[r] * __expf(0.5f * lv1) + mu1;
        }
        __syncwarp();

        // ======== Phase 3: delta = z@Wnext^T, state update, totals ========
        #pragma unroll
        for (int r = 0; r < 2; ++r) {
            const int m = wrp * 2 + r;
            const int b = bBase + m;
            float d0 = bnx_s[lane], d1 = bnx_s[lane + 32];
            #pragma unroll 8
            for (int l = 0; l < LAT; ++l) {
                float zl = zs[l * MS + m];
                d0 = fmaf(zl, wnT[l * 64 + lane],      d0);
                d1 = fmaf(zl, wnT[l * 64 + lane + 32], d1);
            }
            float xn0 = (lane == 0) ? 0.f : fmaxf(xs[lane * MS + m] + d0, 0.f);
            float xn1 = fmaxf(xs[(lane + 32) * MS + m] + d1, 0.f);
            float part = xn0 + xn1;
            #pragma unroll
            for (int s2 = 16; s2 > 0; s2 >>= 1)
                part += __shfl_xor_sync(0xffffffffu, part, s2);
            float add = abuf[m];
            float v0 = (lane == 0) ? add : xn0;
            size_t ob = O_STATES + ((size_t)b * T_STEPS + t) * D_IN;
            out[ob + lane]      = v0;
            out[ob + lane + 32] = xn1;
            xs[lane * MS + m]        = v0;
            xs[(lane + 32) * MS + m] = xn1;
            if (lane == 0) {
                out[O_TPRE  + (size_t)b * 128 + t + 1] = part;
                out[O_TPOST + (size_t)b * 128 + t + 1] = part + add;
            }
        }
        __syncthreads();   // xs/hs/cs stable before next step's phase 1
    }
}

extern "C" void kernel_launch(void* const* d_in, const int* in_sizes, int n_in,
                              void* d_out, int out_size) {
    const float* data  = (const float*)d_in[0];
    const float* locs  = (const float*)d_in[1];
    const float* Wih   = (const float*)d_in[2];
    const float* Whh   = (const float*)d_in[3];
    const float* bih   = (const float*)d_in[4];
    const float* bhh   = (const float*)d_in[5];
    const float* Wmu   = (const float*)d_in[6];
    const float* bmu   = (const float*)d_in[7];
    const float* Wvar  = (const float*)d_in[8];
    const float* bvar  = (const float*)d_in[9];
    const float* Wvelo = (const float*)d_in[10];
    const float* bvelo = (const float*)d_in[11];
    const float* Wsw   = (const float*)d_in[12];
    const float* bsw   = (const float*)d_in[13];
    const float* Wgen  = (const float*)d_in[14];
    const float* bgen  = (const float*)d_in[15];
    const float* Won   = (const float*)d_in[16];
    const float* bon   = (const float*)d_in[17];
    const float* Wnext = (const float*)d_in[18];
    const float* bnext = (const float*)d_in[19];
    const float* Wloc  = (const float*)d_in[20];
    const float* bloc  = (const float*)d_in[21];
    const float* eps   = (const float*)d_in[22];
    float* out = (float*)d_out;

    prep_kernel<<<1, 256>>>(Wgen, bgen, Won, bon, Wvelo, bvelo, Wsw, bsw);
    prep2_kernel<<<256, 512>>>(Wih, Whh, Wmu, Wvar);

    // floats: 28896 (states etc.) + 3 * 8192 (panel slots) = 53472
    const size_t smem_bytes = 53472 * sizeof(float);  // 213,888 B
    cudaFuncSetAttribute(model_kernel,
                         cudaFuncAttributeMaxDynamicSharedMemorySize,
                         (int)smem_bytes);
    model_kernel<<<NCTA, NTH, smem_bytes>>>(data, locs, bih, bhh,
                                            bmu, bvar, Wnext, bnext,
                                            Wloc, bloc, eps, out);
}

// round 8
// speedup vs baseline: 1.2802x; 1.0024x over previous
#include <cuda_runtime.h>

// Model_10582799417658: 127-step LSTM-VAE rollout.
// B=4096, D=64, H=256, GATES=1024, L=64, T=128 (127 scan steps).
//
// Round 7: cp.async (LDGSTS) 3-stage panel ring replaces LDG->reg->STS
// staging. Frees ~20 regs/thread (round 5 was at the 128-reg cap with 64
// accumulator regs -> spills), removes STS issue from the hot loop, and
// bypasses L1 on weight fills. Phase-2a panels deepened to PK2=32 (8 syncs).

#define B_TOT   4096
#define T_STEPS 127
#define D_IN    64
#define HID     256
#define GATE    1024
#define LAT     64
#define BT      32
#define NTH     512
#define NCTA    (B_TOT / BT)   // 128
#define MS      36             // padded m-stride (floats)
#define PK      8              // phase-1 panel depth (k)
#define NP1     40             // 320 / 8
#define PK2     32             // phase-2 panel depth
#define NP2     8              // 256 / 32
#define SLOTF   8192           // floats per panel slot (32 KB)

// ---- output layout ----
#define N_STATES ((unsigned long long)B_TOT * T_STEPS * D_IN)
#define N_GENS   ((unsigned long long)B_TOT * T_STEPS)
#define N_TOTS   ((unsigned long long)B_TOT * 128)
#define O_STATES 0ULL
#define O_GENS   (O_STATES + N_STATES)
#define O_ONOFF  (O_GENS + N_GENS)
#define O_TPRE   (O_ONOFF + N_GENS)
#define O_TPOST  (O_TPRE + N_TOTS)

typedef unsigned long long ull;

__device__ float g_wgv[HID];
__device__ float g_wov[HID];
__device__ float g_b2[2];
// k-major transposed weights (filled once):
// g_Wt1[k][r] = (k<64 ? Wih[r][k] : Whh[r][k-64]),  r in [0,1024), k in [0,320)
// g_Wt2[k][r] = (r<64 ? Wmu[r][k] : Wvar[r-64][k]), r in [0,128),  k in [0,256)
__device__ float g_Wt1[320 * 1024];
__device__ float g_Wt2[256 * 128];

__device__ __forceinline__ ull pack2s(float a) {   // splat (a, a)
    ull r;
    asm("mov.b64 %0, {%1,%1};" : "=l"(r) : "r"(__float_as_uint(a)));
    return r;
}
__device__ __forceinline__ void fma2(ull &d, ull a, ull b) {
    asm("fma.rn.f32x2 %0, %1, %2, %0;" : "+l"(d) : "l"(a), "l"(b));
}
__device__ __forceinline__ float2 unpack2(ull v) {
    unsigned int lo, hi;
    asm("mov.b64 {%0,%1}, %2;" : "=r"(lo), "=r"(hi) : "l"(v));
    float2 f; f.x = __uint_as_float(lo); f.y = __uint_as_float(hi);
    return f;
}
__device__ __forceinline__ float sig_f(float x) {
    return 1.0f / (1.0f + __expf(-x));
}
__device__ __forceinline__ float tanh_f(float x) {
    return 1.0f - 2.0f / (__expf(2.0f * x) + 1.0f);
}
__device__ __forceinline__ void cpa16(unsigned int dst, const void* src) {
    asm volatile("cp.async.cg.shared.global [%0], [%1], 16;" :: "r"(dst), "l"(src));
}
__device__ __forceinline__ void cpa_commit() {
    asm volatile("cp.async.commit_group;");
}
__device__ __forceinline__ void cpa_wait1() {
    asm volatile("cp.async.wait_group 1;");
}

// Fold velo/switch heads into rank-1 vectors.
__global__ void prep_kernel(const float* __restrict__ Wgen, const float* __restrict__ bgen,
                            const float* __restrict__ Won,  const float* __restrict__ bon,
                            const float* __restrict__ Wvelo, const float* __restrict__ bvelo,
                            const float* __restrict__ Wsw,  const float* __restrict__ bsw) {
    int k = threadIdx.x;
    float s1 = 0.f, s2 = 0.f;
    #pragma unroll 4
    for (int l = 0; l < LAT; ++l) {
        s1 += Wgen[l] * Wvelo[l * HID + k];
        s2 += Won[l]  * Wsw[l * HID + k];
    }
    g_wgv[k] = s1;
    g_wov[k] = s2;
    if (k == 0) {
        float b1 = bgen[0], b2 = bon[0];
        for (int l = 0; l < LAT; ++l) {
            b1 += Wgen[l] * bvelo[l];
            b2 += Won[l]  * bsw[l];
        }
        g_b2[0] = b1; g_b2[1] = b2;
    }
}

// One-time k-major weight transpose.
__global__ void prep2_kernel(const float* __restrict__ Wih, const float* __restrict__ Whh,
                             const float* __restrict__ Wmu, const float* __restrict__ Wvar) {
    const int stride = gridDim.x * blockDim.x;
    const int idx = blockIdx.x * blockDim.x + threadIdx.x;
    for (int i = idx; i < 320 * 1024; i += stride) {
        int k = i >> 10, r = i & 1023;
        g_Wt1[i] = (k < 64) ? Wih[r * D_IN + k] : Whh[r * HID + (k - 64)];
    }
    for (int i = idx; i < 256 * 128; i += stride) {
        int k = i >> 7, r = i & 127;
        g_Wt2[i] = (r < 64) ? Wmu[r * HID + k] : Wvar[(r - 64) * HID + k];
    }
}

__global__ void __launch_bounds__(NTH, 1)
model_kernel(const float* __restrict__ data, const float* __restrict__ locs,
             const float* __restrict__ bih,  const float* __restrict__ bhh,
             const float* __restrict__ bmu,  const float* __restrict__ bvar,
             const float* __restrict__ Wnext, const float* __restrict__ bnext,
             const float* __restrict__ Wloc, const float* __restrict__ bloc,
             const float* __restrict__ eps,  float* __restrict__ out) {
    extern __shared__ float sm[];
    float* xs     = sm;                  // [64][MS]
    float* hs     = xs     + 2304;       // [256][MS]  in-place h
    float* cs     = hs     + 9216;       // [256][MS]
    float* zs     = cs     + 9216;       // [64][MS]
    float* bsum   = zs     + 2304;       // [1024]
    float* wgv    = bsum   + 1024;       // [256]
    float* wov    = wgv    + 256;        // [256]
    float* bmu_s  = wov    + 256;        // [64]
    float* bvar_s = bmu_s  + 64;         // [64]
    float* bnx_s  = bvar_s + 64;         // [64]
    float* wnT    = bnx_s  + 64;         // [64][64]
    float* abuf   = wnT    + 4096;       // [32]
    float* wbA    = abuf   + 32;         // 3 panel slots of SLOTF floats
    float* mus    = wbA;                 // [64][MS]  (reuse slot0 after 2a)
    float* lvs    = wbA + 2304;          // [64][MS]

    const unsigned int wb_u32 =
        (unsigned int)__cvta_generic_to_shared(wbA);

    const int tid   = threadIdx.x;
    const int bBase = blockIdx.x * BT;
    // phase-1 compute tile: 4 m-tiles of 8 rows x 128 j-pairs
    const int m0A  = (tid & 3) * 8;
    const int jt2A = (tid >> 2) * 2;
    const int wrp = tid >> 5, lane = tid & 31;
    // phase-2a tile: 8 m-tiles of 4 x 64 row-pairs
    const int m08 = (tid & 7) * 4;
    const int jq2 = (tid >> 3) * 2;

    // ---------------- init ----------------
    for (int i = tid; i < HID * MS; i += NTH) cs[i] = 0.f;
    for (int i = tid; i < D_IN * BT; i += NTH) {
        int k = i / BT, m = i % BT;
        xs[k * MS + m] = data[(size_t)(bBase + m) * (128 * D_IN) + k];
    }
    for (int i = tid; i < HID * BT; i += NTH) {
        int j = i / BT, m = i % BT;
        int b = bBase + m;
        hs[j * MS + m] = locs[b * 2] * Wloc[j * 2] + locs[b * 2 + 1] * Wloc[j * 2 + 1] + bloc[j];
    }
    for (int i = tid; i < GATE; i += NTH) bsum[i] = bih[i] + bhh[i];
    for (int i = tid; i < HID; i += NTH) { wgv[i] = g_wgv[i]; wov[i] = g_wov[i]; }
    for (int i = tid; i < LAT; i += NTH) { bmu_s[i] = bmu[i]; bvar_s[i] = bvar[i]; }
    for (int i = tid; i < D_IN; i += NTH) bnx_s[i] = bnext[i];
    for (int i = tid; i < LAT * D_IN; i += NTH) {   // wnT[l][c] = Wnext[c][l]
        int l = i >> 6, c = i & 63;
        wnT[i] = Wnext[c * LAT + l];
    }
    if (tid < BT) {
        out[O_TPRE  + (size_t)(bBase + tid) * 128] = 0.f;
        out[O_TPOST + (size_t)(bBase + tid) * 128] = 0.f;
    }
    const float bgv = g_b2[0], bov = g_b2[1];
    __syncthreads();

    // panel issue helpers (cp.async, 16B granules)
    auto issue1 = [&](int p, int slot) {
        const float4* src = ((const float4*)g_Wt1) + (size_t)p * 2048 + tid;
        unsigned int dst = wb_u32 + (unsigned int)slot * (SLOTF * 4u) + tid * 16u;
        cpa16(dst,          src);
        cpa16(dst + 8192u,  src + 512);
        cpa16(dst + 16384u, src + 1024);
        cpa16(dst + 24576u, src + 1536);
    };
    auto issue2 = [&](int p, int slot) {
        const float4* src = ((const float4*)g_Wt2) + (size_t)p * 1024 + tid;
        unsigned int dst = wb_u32 + (unsigned int)slot * (SLOTF * 4u) + tid * 16u;
        cpa16(dst,         src);
        cpa16(dst + 8192u, src + 512);
    };

    for (int t = 0; t < T_STEPS; ++t) {
        // prefetch eps for phase 2b
        float ea[2], eb[2];
        {
            const int mr = wrp * 2;
            const float* ep = eps + ((size_t)t * B_TOT + bBase + mr) * LAT;
            ea[0] = __ldg(ep + lane);        eb[0] = __ldg(ep + lane + 32);
            ea[1] = __ldg(ep + LAT + lane);  eb[1] = __ldg(ep + LAT + lane + 32);
        }

        // ======== Phase 1: gates = x@Wih^T + h@Whh^T, LSTM update ========
        {
            issue1(0, 0); cpa_commit();
            issue1(1, 1); cpa_commit();

            ull acc[32];
            #pragma unroll
            for (int i = 0; i < 32; ++i) acc[i] = 0ULL;

            for (int p = 0; p < NP1; ++p) {
                cpa_wait1();
                __syncthreads();     // panel p visible; slot (p+2)%3 free
                if (p + 2 < NP1) issue1(p + 2, (p + 2) % 3);
                cpa_commit();
                const float* wc = wbA + (p % 3) * SLOTF;
                const float* Ab = (p < 8) ? (xs + p * PK * MS)
                                          : (hs + (p * PK - 64) * MS);
                #pragma unroll
                for (int kk = 0; kk < PK; ++kk) {
                    float4 a0 = *(const float4*)(Ab + kk * MS + m0A);
                    float4 a1 = *(const float4*)(Ab + kk * MS + m0A + 4);
                    const float* wr = wc + kk * 1024 + jt2A;
                    ull w0 = *(const ull*)(wr);
                    ull w1 = *(const ull*)(wr + 256);
                    ull w2 = *(const ull*)(wr + 512);
                    ull w3 = *(const ull*)(wr + 768);
                    #pragma unroll
                    for (int m = 0; m < 4; ++m) {
                        ull am = pack2s((&a0.x)[m]);
                        fma2(acc[m * 4 + 0], am, w0);
                        fma2(acc[m * 4 + 1], am, w1);
                        fma2(acc[m * 4 + 2], am, w2);
                        fma2(acc[m * 4 + 3], am, w3);
                    }
                    #pragma unroll
                    for (int m = 0; m < 4; ++m) {
                        ull am = pack2s((&a1.x)[m]);
                        fma2(acc[(m + 4) * 4 + 0], am, w0);
                        fma2(acc[(m + 4) * 4 + 1], am, w1);
                        fma2(acc[(m + 4) * 4 + 2], am, w2);
                        fma2(acc[(m + 4) * 4 + 3], am, w3);
                    }
                }
            }
            __syncthreads();         // all warps done reading hs/panels

            // epilogue: bias + LSTM nonlinearity, h/c in place
            const int hj0 = jt2A, hj1 = jt2A + 1;
            const float bi0 = bsum[hj0],       bi1 = bsum[hj1];
            const float bf0 = bsum[256 + hj0], bf1 = bsum[256 + hj1];
            const float bg0 = bsum[512 + hj0], bg1 = bsum[512 + hj1];
            const float bo0 = bsum[768 + hj0], bo1 = bsum[768 + hj1];
            #pragma unroll
            for (int m = 0; m < 8; ++m) {
                const int mm = m0A + m;
                float2 vi = unpack2(acc[m * 4 + 0]);
                float2 vf = unpack2(acc[m * 4 + 1]);
                float2 vg = unpack2(acc[m * 4 + 2]);
                float2 vo = unpack2(acc[m * 4 + 3]);
                {
                    float iv = sig_f(vi.x + bi0), fv = sig_f(vf.x + bf0);
                    float gv = tanh_f(vg.x + bg0), ov = sig_f(vo.x + bo0);
                    float c = fv * cs[hj0 * MS + mm] + iv * gv;
                    cs[hj0 * MS + mm] = c;
                    hs[hj0 * MS + mm] = ov * tanh_f(c);
                }
                {
                    float iv = sig_f(vi.y + bi1), fv = sig_f(vf.y + bf1);
                    float gv = tanh_f(vg.y + bg1), ov = sig_f(vo.y + bo1);
                    float c = fv * cs[hj1 * MS + mm] + iv * gv;
                    cs[hj1 * MS + mm] = c;
                    hs[hj1 * MS + mm] = ov * tanh_f(c);
                }
            }
        }

        // ======== Phase 2a: [mu;logvar] = h @ [Wmu;Wvar]^T ========
        {
            issue2(0, 0); cpa_commit();
            issue2(1, 1); cpa_commit();

            ull acc2[4] = {0ULL, 0ULL, 0ULL, 0ULL};

            for (int p = 0; p < NP2; ++p) {
                cpa_wait1();
                __syncthreads();     // also orders phase-1 hs writes at p=0
                if (p + 2 < NP2) issue2(p + 2, (p + 2) % 3);
                cpa_commit();
                const float* wc = wbA + (p % 3) * SLOTF;
                const int k0 = p * PK2;
                #pragma unroll
                for (int kk = 0; kk < PK2; ++kk) {
                    float4 a = *(const float4*)(hs + (k0 + kk) * MS + m08);
                    ull w = *(const ull*)(wc + kk * 128 + jq2);
                    fma2(acc2[0], pack2s(a.x), w);
                    fma2(acc2[1], pack2s(a.y), w);
                    fma2(acc2[2], pack2s(a.z), w);
                    fma2(acc2[3], pack2s(a.w), w);
                }
            }
            __syncthreads();         // all warps done with panel slots

            // epilogue: row pair (jq2, jq2+1) for 4 m rows -> mus/lvs (slot0)
            if (jq2 < 64) {
                const float b0 = bmu_s[jq2], b1 = bmu_s[jq2 + 1];
                #pragma unroll
                for (int m = 0; m < 4; ++m) {
                    float2 v = unpack2(acc2[m]);
                    mus[jq2 * MS + m08 + m]       = v.x + b0;
                    mus[(jq2 + 1) * MS + m08 + m] = v.y + b1;
                }
            } else {
                const int l0 = jq2 - 64;
                const float b0 = bvar_s[l0], b1 = bvar_s[l0 + 1];
                #pragma unroll
                for (int m = 0; m < 4; ++m) {
                    float2 v = unpack2(acc2[m]);
                    lvs[l0 * MS + m08 + m]       = v.x + b0;
                    lvs[(l0 + 1) * MS + m08 + m] = v.y + b1;
                }
            }
        }
        __syncthreads();

        // ======== Phase 2b: gen/on + reparameterized z ========
        #pragma unroll
        for (int r = 0; r < 2; ++r) {
            const int m = wrp * 2 + r;
            const int b = bBase + m;
            float gp = 0.f, op = 0.f;
            #pragma unroll
            for (int i2 = 0; i2 < 8; ++i2) {
                int k = lane + 32 * i2;
                float hv = hs[k * MS + m];
                gp = fmaf(hv, wgv[k], gp);
                op = fmaf(hv, wov[k], op);
            }
            #pragma unroll
            for (int s2 = 16; s2 > 0; s2 >>= 1) {
                gp += __shfl_xor_sync(0xffffffffu, gp, s2);
                op += __shfl_xor_sync(0xffffffffu, op, s2);
            }
            if (lane == 0) {
                float gen = fmaxf(gp + bgv, 0.f);
                float on  = (op + bov) > 0.f ? 1.f : 0.f;
                abuf[m] = gen * on;
                out[O_GENS  + (size_t)b * T_STEPS + t] = gen;
                out[O_ONOFF + (size_t)b * T_STEPS + t] = on;
            }
            float mu0 = mus[lane * MS + m],        lv0 = lvs[lane * MS + m];
            float mu1 = mus[(lane + 32) * MS + m], lv1 = lvs[(lane + 32) * MS + m];
            zs[lane * MS + m]        = ea[r] * __expf(0.5f * lv0) + mu0;
            zs[(lane + 32) * MS + m] = eb[r] * __expf(0.5f * lv1) + mu1;
        }
        __syncwarp();

        // ======== Phase 3: delta = z@Wnext^T, state update, totals ========
        #pragma unroll
        for (int r = 0; r < 2; ++r) {
            const int m = wrp * 2 + r;
            const int b = bBase + m;
            float d0 = bnx_s[lane], d1 = bnx_s[lane + 32];
            #pragma unroll 8
            for (int l = 0; l < LAT; ++l) {
                float zl = zs[l * MS + m];
                d0 = fmaf(zl, wnT[l * 64 + lane],      d0);
                d1 = fmaf(zl, wnT[l * 64 + lane + 32], d1);
            }
            float xn0 = (lane == 0) ? 0.f : fmaxf(xs[lane * MS + m] + d0, 0.f);
            float xn1 = fmaxf(xs[(lane + 32) * MS + m] + d1, 0.f);
            float part = xn0 + xn1;
            #pragma unroll
            for (int s2 = 16; s2 > 0; s2 >>= 1)
                part += __shfl_xor_sync(0xffffffffu, part, s2);
            float add = abuf[m];
            float v0 = (lane == 0) ? add : xn0;
            size_t ob = O_STATES + ((size_t)b * T_STEPS + t) * D_IN;
            out[ob + lane]      = v0;
            out[ob + lane + 32] = xn1;
            xs[lane * MS + m]        = v0;
            xs[(lane + 32) * MS + m] = xn1;
            if (lane == 0) {
                out[O_TPRE  + (size_t)b * 128 + t + 1] = part;
                out[O_TPOST + (size_t)b * 128 + t + 1] = part + add;
            }
        }
        __syncthreads();   // xs/hs/cs stable before next step's phase 1
    }
}

extern "C" void kernel_launch(void* const* d_in, const int* in_sizes, int n_in,
                              void* d_out, int out_size) {
    const float* data  = (const float*)d_in[0];
    const float* locs  = (const float*)d_in[1];
    const float* Wih   = (const float*)d_in[2];
    const float* Whh   = (const float*)d_in[3];
    const float* bih   = (const float*)d_in[4];
    const float* bhh   = (const float*)d_in[5];
    const float* Wmu   = (const float*)d_in[6];
    const float* bmu   = (const float*)d_in[7];
    const float* Wvar  = (const float*)d_in[8];
    const float* bvar  = (const float*)d_in[9];
    const float* Wvelo = (const float*)d_in[10];
    const float* bvelo = (const float*)d_in[11];
    const float* Wsw   = (const float*)d_in[12];
    const float* bsw   = (const float*)d_in[13];
    const float* Wgen  = (const float*)d_in[14];
    const float* bgen  = (const float*)d_in[15];
    const float* Won   = (const float*)d_in[16];
    const float* bon   = (const float*)d_in[17];
    const float* Wnext = (const float*)d_in[18];
    const float* bnext = (const float*)d_in[19];
    const float* Wloc  = (const float*)d_in[20];
    const float* bloc  = (const float*)d_in[21];
    const float* eps   = (const float*)d_in[22];
    float* out = (float*)d_out;

    prep_kernel<<<1, 256>>>(Wgen, bgen, Won, bon, Wvelo, bvelo, Wsw, bsw);
    prep2_kernel<<<256, 512>>>(Wih, Whh, Wmu, Wvar);

    // floats: 28896 (states etc.) + 3 * 8192 (panel slots) = 53472
    const size_t smem_bytes = 53472 * sizeof(float);  // 213,888 B
    cudaFuncSetAttribute(model_kernel,
                         cudaFuncAttributeMaxDynamicSharedMemorySize,
                         (int)smem_bytes);
    model_kernel<<<NCTA, NTH, smem_bytes>>>(data, locs, bih, bhh,
                                            bmu, bvar, Wnext, bnext,
                                            Wloc, bloc, eps, out);
}